// round 12
// baseline (speedup 1.0000x reference)
#include <cuda_runtime.h>

// GeneratorCell: B=128, M=32 queue rows, N=64 strokes, K=2048 stroke length
// grid = 256: CTA = (batch, half). Each CTA computes the coef chain (duplicated,
// cheap) and half the FIR output range. 2 CTAs/SM overlap each other's stalls.
#define Bn 128
#define Mn 32
#define Nn 64
#define Kn 2048
#define NT 96                      // 3 warps per CTA
#define Cn 11                      // 96*11 = 1056 outputs per CTA = SEG
#define SEG 1056                   // outputs per half; 2*SEG = 2112 = N + M*N
#define LPAD 66                    // local emb pad below
#define ESZ 1128                   // LPAD + SEG + 6, rounded to float4 (564 float4)

typedef unsigned long long ull;

__device__ __forceinline__ float sigmoidf_(float x) { return 1.0f / (1.0f + __expf(-x)); }

__device__ __forceinline__ ull pack2(float x, float y) {
    ull r; asm("mov.b64 %0, {%1,%2};" : "=l"(r) : "f"(x), "f"(y)); return r;
}
__device__ __forceinline__ void unpack2(ull v, float& x, float& y) {
    asm("mov.b64 {%0,%1}, %2;" : "=f"(x), "=f"(y) : "l"(v));
}
__device__ __forceinline__ ull ffma2(ull a, ull b, ull c) {   // packed f32x2 FMA (sm_100+)
    ull d; asm("fma.rn.f32x2 %0, %1, %2, %3;" : "=l"(d) : "l"(a), "l"(b), "l"(c)); return d;
}

__global__ __launch_bounds__(NT) void gen_cell_kernel(
    const float* __restrict__ qt1,      // [B, M, N, 2]
    const float* __restrict__ ht1,      // [B, N, 2]
    const float* __restrict__ zt,       // [B, N]
    const float* __restrict__ alpha_t,  // [B, N]
    const float* __restrict__ conv_w,   // [2, 2, M+1, 1]
    const float* __restrict__ conv_b,   // [2]
    const float* __restrict__ W_xr, const float* __restrict__ W_hr, const float* __restrict__ b_r,
    const float* __restrict__ W_xu, const float* __restrict__ W_hu, const float* __restrict__ b_u,
    const float* __restrict__ W_xn, const float* __restrict__ W_hn, const float* __restrict__ b_n,
    const float* __restrict__ lin_w,    // [N, 2N]
    const float* __restrict__ lin_b,    // [N]
    const float* __restrict__ W_emb,    // [K, 2]
    float* __restrict__ out)            // st [B,N,2] | qt [B,M,N,2] | ht [B,N,2]
{
    __shared__ __align__(16) ull    s_exy[ESZ];     // local emb window (~9KB), zero-guarded
    __shared__ float2 s_part[3 * Nn];               // conv partials [group][n]
    __shared__ ull    s_coef2[Nn + 2];              // coef padded to 66 (= 6*11)
    __shared__ __align__(16) float s_ht[2 * Nn];

    const int bid  = blockIdx.x;
    const int b    = bid >> 1;
    const int half = bid & 1;
    const int tid  = threadIdx.x;
    const int lane = tid & 31;
    const int wrp  = tid >> 5;                      // 0..2
    const int LO   = half * SEG - LPAD;             // global emb idx of local l=0 (even)
    const float2* qf = (const float2*)(qt1 + (size_t)b * Mn * Nn * 2);

    // ============ phase 0: emb window staging + conv partials ============
    {
        // -- stage this half's emb window: 564 float4, guarded against [0,K) --
        const float4* we4 = (const float4*)W_emb;   // 1024 float4 = 2048 (x,y) pairs
        float4* exy4 = (float4*)s_exy;
        #pragma unroll
        for (int k = 0; k < 6; k++) {
            const int i4 = tid + k * NT;            // float4 index; covers 2 emb entries
            if (i4 < ESZ / 2) {
                const int g0 = LO + 2 * i4;         // even; pair (g0, g0+1)
                float4 e = make_float4(0.f, 0.f, 0.f, 0.f);
                if (g0 >= 0 && g0 < Kn) e = we4[g0 >> 1];
                exy4[i4] = e;
            }
        }

        // -- conv: 3 tap-groups (warp = group) x 32 threads; each thread 2 strokes --
        const int g = wrp;                          // tap group, 11 taps
        const int s = lane;                         // strokes s and s+32
        float2 v0[11], v1[11];
        #pragma unroll
        for (int k = 0; k < 11; k++) {
            const int h = g * 11 + k;
            if (h < 32) {
                v0[k] = qf[h * Nn + s];
                v1[k] = qf[h * Nn + s + 32];
            } else {                                // h == 32: ht1 row
                v0[k] = ((const float2*)ht1)[b * Nn + s];
                v1[k] = ((const float2*)ht1)[b * Nn + s + 32];
            }
        }
        float a0A = 0.f, a0B = 0.f, a1A = 0.f, a1B = 0.f;   // stroke s, dual chains
        float b0A = 0.f, b0B = 0.f, b1A = 0.f, b1B = 0.f;   // stroke s+32
        #pragma unroll
        for (int k = 0; k < 11; k++) {
            const int h = g * 11 + k;
            const float wa = conv_w[h],      wb = conv_w[33 + h];
            const float wc = conv_w[66 + h], wd = conv_w[99 + h];
            if (k & 1) {
                a0B = fmaf(v0[k].x, wa, fmaf(v0[k].y, wb, a0B));
                a1B = fmaf(v0[k].x, wc, fmaf(v0[k].y, wd, a1B));
                b0B = fmaf(v1[k].x, wa, fmaf(v1[k].y, wb, b0B));
                b1B = fmaf(v1[k].x, wc, fmaf(v1[k].y, wd, b1B));
            } else {
                a0A = fmaf(v0[k].x, wa, fmaf(v0[k].y, wb, a0A));
                a1A = fmaf(v0[k].x, wc, fmaf(v0[k].y, wd, a1A));
                b0A = fmaf(v1[k].x, wa, fmaf(v1[k].y, wb, b0A));
                b1A = fmaf(v1[k].x, wc, fmaf(v1[k].y, wd, b1A));
            }
        }
        s_part[g * Nn + s]      = make_float2(a0A + a0B, a1A + a1B);
        s_part[g * Nn + s + 32] = make_float2(b0A + b0B, b1A + b1B);
    }
    __syncthreads();

    // ---- preload lin_w slices for this warp's first 11 matvec rows (hides under GRU) ----
    float4 lv[11];
    {
        const float4* lw4 = (const float4*)lin_w;   // [64 rows][32 float4]
        #pragma unroll
        for (int k = 0; k < 11; k++) {
            const int row = wrp * 22 + k;
            lv[k] = (row < Nn) ? lw4[row * 32 + lane] : make_float4(0.f, 0.f, 0.f, 0.f);
        }
    }

    // ---- preload FIR circular window (LDS latency hides under GRU) ----
    // logical w[i] = emb_local[LPAD + p_loc + i] lives at P[(11-i)%11]
    const int p_loc = tid * Cn;                     // local output offset in [0, SEG)
    ull acc[Cn], P[Cn];
    #pragma unroll
    for (int i = 0; i < Cn; i++) {
        P[(Cn - i) % Cn] = s_exy[LPAD + p_loc + i];
        acc[i] = 0ULL;
    }

    // ============ phase 1: GRU per stroke (tid<64; warps 0-1) ============
    if (tid < 64) {
        const int n = tid;
        const float2 hv = ((const float2*)ht1)[b * Nn + n];   // L1 hit
        const float2 pa = s_part[n], pb = s_part[Nn + n], pc = s_part[2 * Nn + n];
        const float h0 = (pa.x + pb.x) + pc.x + conv_b[0];    // ht1 tap already in pc
        const float h1 = (pa.y + pb.y) + pc.y + conv_b[1];

        const float x0 = zt[b * Nn + n];
        const float x1 = alpha_t[b * Nn + n];

        float r0 = sigmoidf_(fmaf(x0, W_xr[0], fmaf(x1, W_xr[2], fmaf(h0, W_hr[0], fmaf(h1, W_hr[2], b_r[0])))));
        float r1 = sigmoidf_(fmaf(x0, W_xr[1], fmaf(x1, W_xr[3], fmaf(h0, W_hr[1], fmaf(h1, W_hr[3], b_r[1])))));
        float u0 = sigmoidf_(fmaf(x0, W_xu[0], fmaf(x1, W_xu[2], fmaf(h0, W_hu[0], fmaf(h1, W_hu[2], b_u[0])))));
        float u1 = sigmoidf_(fmaf(x0, W_xu[1], fmaf(x1, W_xu[3], fmaf(h0, W_hu[1], fmaf(h1, W_hu[3], b_u[1])))));

        const float rh0 = r0 * h0, rh1 = r1 * h1;
        float nt0 = tanhf(fmaf(x0, W_xn[0], fmaf(x1, W_xn[2], fmaf(rh0, W_hn[0], fmaf(rh1, W_hn[2], b_n[0])))));
        float nt1 = tanhf(fmaf(x0, W_xn[1], fmaf(x1, W_xn[3], fmaf(rh0, W_hn[1], fmaf(rh1, W_hn[3], b_n[1])))));

        const float hn0 = u0 * hv.x + (1.0f - u0) * nt0;
        const float hn1 = u1 * hv.y + (1.0f - u1) * nt1;

        s_ht[2 * n + 0] = hn0;
        s_ht[2 * n + 1] = hn1;

        if (!half) {                                 // write ht once (half 0)
            const size_t off_ht = (size_t)Bn * Nn * 2 + (size_t)Bn * Mn * Nn * 2;
            ((float2*)(out + off_ht))[(size_t)b * Nn + n] = make_float2(hn0, hn1);
        }
    }
    __syncthreads();

    // ============ phase 2: coef matvec, 3 warps x 22 rows, shuffle reduce ============
    {
        const float4 ht4 = ((const float4*)s_ht)[lane];
        const float4* lw4 = (const float4*)lin_w;
        if (tid >= 94) s_coef2[Nn + (tid - 94)] = 0ULL;       // coef zero pads (rows 64,65)
        #pragma unroll
        for (int k = 0; k < 22; k++) {
            const int row = wrp * 22 + k;
            if (row < Nn) {
                const float4 l = (k < 11) ? lv[k] : lw4[row * 32 + lane];
                float d = fmaf(l.x, ht4.x, fmaf(l.y, ht4.y, fmaf(l.z, ht4.z, l.w * ht4.w)));
                d += __shfl_xor_sync(0xffffffffu, d, 16);
                d += __shfl_xor_sync(0xffffffffu, d, 8);
                d += __shfl_xor_sync(0xffffffffu, d, 4);
                d += __shfl_xor_sync(0xffffffffu, d, 2);
                d += __shfl_xor_sync(0xffffffffu, d, 1);
                if (lane == 0) {
                    const float c = (d + lin_b[row]) * alpha_t[b * Nn + row];
                    s_coef2[row] = pack2(c, c);
                }
            }
        }
    }
    __syncthreads();

    // ============ phase 3: FIR, circular buffer, 6 rolled blocks x 11 unrolled ============
    // At iteration n: logical w[i] = emb_local[LPAD + p_loc + i - n] at P[(n-i) mod 11].
    #pragma unroll 1
    for (int blk = 0; blk < 6; blk++) {
        const int nb = blk * Cn;
        #pragma unroll
        for (int j = 0; j < Cn; j++) {
            const ull c2 = s_coef2[nb + j];         // broadcast (rows 64,65 zero)
            acc[10] = ffma2(c2, P[(j + 1) % Cn], acc[10]);
            P[(j + 1) % Cn] = s_exy[LPAD + p_loc - (nb + j) - 1];   // min idx = p_loc >= 0
            #pragma unroll
            for (int i = 9; i >= 0; i--)
                acc[i] = ffma2(c2, P[(j - i + 22) % Cn], acc[i]);
        }
    }

    // ============ output assembly ============
    float2* st_out = (float2*)out + (size_t)b * Nn;
    float2* qt_out = (float2*)(out + (size_t)Bn * Nn * 2) + (size_t)b * Mn * Nn;
    #pragma unroll
    for (int i = 0; i < Cn; i++) {
        const int p = half * SEG + p_loc + i;       // global output position
        float fx, fy; unpack2(acc[i], fx, fy);
        float2 qv = make_float2(0.0f, 0.0f);
        if (p < Mn * Nn) qv = qf[p];                // L1-hot (loaded by conv)
        float2 r = make_float2(qv.x + fx, qv.y + fy);
        if (p < Nn) st_out[p] = r;                  // st = q_row0 + f[:N]
        else        qt_out[p - Nn] = r;             // qt = q_shift + tail
    }
}

extern "C" void kernel_launch(void* const* d_in, const int* in_sizes, int n_in,
                              void* d_out, int out_size) {
    const float* qt1     = (const float*)d_in[0];
    const float* ht1     = (const float*)d_in[1];
    const float* zt      = (const float*)d_in[2];
    const float* alpha_t = (const float*)d_in[3];
    const float* conv_w  = (const float*)d_in[4];
    const float* conv_b  = (const float*)d_in[5];
    const float* W_xr    = (const float*)d_in[6];
    const float* W_hr    = (const float*)d_in[7];
    const float* b_r     = (const float*)d_in[8];
    const float* W_xu    = (const float*)d_in[9];
    const float* W_hu    = (const float*)d_in[10];
    const float* b_u     = (const float*)d_in[11];
    const float* W_xn    = (const float*)d_in[12];
    const float* W_hn    = (const float*)d_in[13];
    const float* b_n     = (const float*)d_in[14];
    const float* lin_w   = (const float*)d_in[15];
    const float* lin_b   = (const float*)d_in[16];
    const float* W_emb   = (const float*)d_in[17];

    gen_cell_kernel<<<2 * Bn, NT>>>(qt1, ht1, zt, alpha_t, conv_w, conv_b,
                                    W_xr, W_hr, b_r, W_xu, W_hu, b_u,
                                    W_xn, W_hn, b_n, lin_w, lin_b, W_emb,
                                    (float*)d_out);
}